// round 16
// baseline (speedup 1.0000x reference)
#include <cuda_runtime.h>
#include <cuda_bf16.h>
#include <cuda_fp16.h>
#include <math.h>
#include <stdint.h>

#define BB 64
#define SS 256
#define HH 1024
#define EE 512
#define GG 4096
#define NCTA 128
#define UPC 8     // hidden units per CTA

// ---- k_steps smem: 6 stages (3 per kgroup) of 34816:
//   stage: A(64 x 272B) | B(64 x 272B) at +17408
// Partial-D tiles are OVERLAID on stage buffers (valid only between the
// post-loop __syncthreads and the pre-barrier __syncthreads):
//   D1(kg) 64x66 f32 at stage kg*3 + 0;  D2(kg) 64x34 f32 at +16896
#define STG64 34816
#define SP_OFF  208896  // P0 prefetch 64 x 32 f32 = 8192
#define SC0_OFF 217088  // c0 state 512 f32
#define SC1_OFF 219136  // c1 state 512 f32
#define SB1_OFF 221184  // layer1 bias 32 f32
#define DYN_STEPS 221312

// ---- k_pre smem: 2 stages of 34816, tokens after
#define PC_STG 34816
#define PC_TOK 69632
#define DYN_PRE 69888

// -------- device-global scratch --------
__device__ float g_P0[(size_t)SS * BB * GG];
__device__ float g_sp[BB * GG];
__device__ __half g_h0[2][BB * HH];
__device__ __half g_h1[2][BB * HH];
__device__ __align__(16) __half g_emb16[(size_t)32000 * EE];
__device__ __align__(16) __half g_Wx[(size_t)GG * EE];
// combined G1 tile: [cta][chunk 0..7][64n x 128k]  (rows 0-31 W_hh0, 32-63 W_ih1)
__device__ __align__(16) __half g_BW01[(size_t)NCTA * 8 * 8192];
// G2 tile: [cta][chunk 0..7][32n x 128k]  (W_hh1)
__device__ __align__(16) __half g_BW11[(size_t)NCTA * 8 * 4096];
// grid barrier state
__device__ unsigned g_bcnt;
__device__ unsigned g_bgen;

union P8 { __half h[8]; uint4 v; };

__device__ __forceinline__ float sigf(float x) { return 1.0f / (1.0f + expf(-x)); }

__device__ __forceinline__ uint32_t smem_u32(const void* p) {
    uint32_t a;
    asm("{ .reg .u64 t; cvta.to.shared.u64 t, %1; cvt.u32.u64 %0, t; }" : "=r"(a) : "l"(p));
    return a;
}
__device__ __forceinline__ void cpa16(uint32_t d, const void* s) {
    asm volatile("cp.async.cg.shared.global [%0], [%1], 16;" :: "r"(d), "l"(s));
}
#define CP_COMMIT() asm volatile("cp.async.commit_group;" ::: "memory")
template<int N> __device__ __forceinline__ void cp_wait() {
    asm volatile("cp.async.wait_group %0;" :: "n"(N) : "memory");
}
__device__ __forceinline__ void bar_kg(int kg) {
    asm volatile("bar.sync %0, 256;" :: "r"(kg + 1) : "memory");
}

__device__ __forceinline__ void ldsm4(uint32_t* r, uint32_t a) {
    asm volatile("ldmatrix.sync.aligned.m8n8.x4.shared.b16 {%0,%1,%2,%3}, [%4];"
                 : "=r"(r[0]), "=r"(r[1]), "=r"(r[2]), "=r"(r[3]) : "r"(a));
}
__device__ __forceinline__ void mma_f16(float* d, const uint32_t* a, uint32_t b0, uint32_t b1) {
    asm volatile(
        "mma.sync.aligned.m16n8k16.row.col.f32.f16.f16.f32 "
        "{%0,%1,%2,%3}, {%4,%5,%6,%7}, {%8,%9}, {%0,%1,%2,%3};"
        : "+f"(d[0]), "+f"(d[1]), "+f"(d[2]), "+f"(d[3])
        : "r"(a[0]), "r"(a[1]), "r"(a[2]), "r"(a[3]), "r"(b0), "r"(b1));
}

// grid-wide barrier: all 128 CTAs co-resident (1/SM on 148 SMs).
// Waiters poll with ld.acquire (no atomic-ALU serialization); arriver
// publishes with st.release.
__device__ __forceinline__ void grid_bar(int tid, unsigned gen) {
    __threadfence();
    __syncthreads();
    if (tid == 0) {
        if (atomicAdd(&g_bcnt, 1u) == NCTA - 1) {
            atomicExch(&g_bcnt, 0u);
            asm volatile("st.global.release.gpu.u32 [%0], %1;"
                         :: "l"(&g_bgen), "r"(gen) : "memory");
        } else {
            unsigned v;
            do {
                asm volatile("ld.global.acquire.gpu.u32 %0, [%1];"
                             : "=r"(v) : "l"(&g_bgen) : "memory");
            } while (v < gen);
        }
    }
    __syncthreads();
}

// =====================================================================
// k_emb16: embed fp32 -> fp16 (one-time)
// =====================================================================
__global__ void __launch_bounds__(256) k_emb16(const float* __restrict__ embed) {
    size_t i = ((size_t)blockIdx.x * 256 + threadIdx.x) * 8;
    float x[8];
    *reinterpret_cast<float4*>(x)     = *reinterpret_cast<const float4*>(embed + i);
    *reinterpret_cast<float4*>(x + 4) = *reinterpret_cast<const float4*>(embed + i + 4);
    P8 p;
#pragma unroll
    for (int u = 0; u < 8; u++) p.h[u] = __float2half(x[u]);
    *reinterpret_cast<uint4*>(g_emb16 + i) = p.v;
}

// =====================================================================
// k_static (proven, unchanged)
// =====================================================================
__global__ void __launch_bounds__(256) k_static(
    const float* __restrict__ enc_outs, const int* __restrict__ src_lang,
    const float* __restrict__ embed, const float* __restrict__ W0,
    const float* __restrict__ b_ih0, const float* __restrict__ b_hh0) {
    __shared__ float sC[8][EE];
    __shared__ float sL[8][EE];
    const int tid = threadIdx.x;
    const int b0 = blockIdx.y * 8;
    for (int i = tid; i < 8 * EE; i += 256) {
        int b = i >> 9, k = i & (EE - 1);
        sC[b][k] = enc_outs[((size_t)(b0 + b) * 128 + 127) * EE + k];
        sL[b][k] = embed[(size_t)src_lang[b0 + b] * EE + k];
    }
    __syncthreads();
    const int g = blockIdx.x * 256 + tid;
    const float* wr = W0 + (size_t)g * 1536;
    float acc[8];
#pragma unroll
    for (int i = 0; i < 8; i++) acc[i] = 0.0f;
    for (int k = 0; k < EE; k += 4) {
        float4 wc = *reinterpret_cast<const float4*>(wr + 512 + k);
        float4 wl = *reinterpret_cast<const float4*>(wr + 1024 + k);
#pragma unroll
        for (int b = 0; b < 8; b++) {
            float4 c4 = *reinterpret_cast<const float4*>(&sC[b][k]);
            float4 l4 = *reinterpret_cast<const float4*>(&sL[b][k]);
            acc[b] += wc.x * c4.x + wc.y * c4.y + wc.z * c4.z + wc.w * c4.w;
            acc[b] += wl.x * l4.x + wl.y * l4.y + wl.z * l4.z + wl.w * l4.w;
        }
    }
    float bias = b_ih0[g] + b_hh0[g];
#pragma unroll
    for (int b = 0; b < 8; b++) g_sp[(b0 + b) * GG + g] = acc[b] + bias;
}

// =====================================================================
// k_prep: grid (8, NCTA, 4)  (unchanged from R15)
// =====================================================================
__global__ void __launch_bounds__(256) k_prep(
    const float* __restrict__ W_hh0, const float* __restrict__ W_ih1,
    const float* __restrict__ W_hh1, const float* __restrict__ W_ih0,
    const float* __restrict__ enc_h) {
    const int c = blockIdx.x, cta = blockIdx.y, which = blockIdx.z, tid = threadIdx.x;

    if (which == 3) {
        int flat = cta * 8 + c;
        int row = flat * 4 + (tid >> 6);
        int col = (tid & 63) * 8;
        const float* s = W_ih0 + (size_t)row * 1536 + col;
        float x[8];
        *reinterpret_cast<float4*>(x)     = *reinterpret_cast<const float4*>(s);
        *reinterpret_cast<float4*>(x + 4) = *reinterpret_cast<const float4*>(s + 4);
        P8 p;
#pragma unroll
        for (int u = 0; u < 8; u++) p.h[u] = __float2half(x[u]);
        *reinterpret_cast<uint4*>(g_Wx + (size_t)row * EE + col) = p.v;
        return;
    }

    if (which == 0) {
        int flat = cta * 8 + c;
        if (flat == 0 && tid == 0) { g_bcnt = 0; g_bgen = 0; }
        if (flat < 256) {
            int i = flat * 256 + tid;
            const int n = BB * HH;
            g_h0[1][i] = __float2half(enc_h[i]);      // H0[-1] lives in buf 1
            g_h1[1][i] = __float2half(enc_h[n + i]);  // H1[-1] lives in buf 1
        }
    }

    const float* W = (which == 0) ? W_hh0 : (which == 1) ? W_ih1 : W_hh1;
    const int nloc = tid >> 3, ks = (tid & 7) * 16;
    const int grow = (nloc >> 3) * HH + cta * UPC + (nloc & 7);
    const float* s = W + (size_t)grow * HH + c * 128 + ks;
    float x[16];
#pragma unroll
    for (int i = 0; i < 4; i++)
        *reinterpret_cast<float4*>(x + 4 * i) = *reinterpret_cast<const float4*>(s + 4 * i);
    P8 p0, p1;
#pragma unroll
    for (int u = 0; u < 8; u++) { p0.h[u] = __float2half(x[u]); p1.h[u] = __float2half(x[8 + u]); }
    __half* G;
    size_t base;
    if (which == 0)      { G = g_BW01; base = ((size_t)cta * 8 + c) * 8192; }
    else if (which == 1) { G = g_BW01; base = ((size_t)cta * 8 + c) * 8192 + 4096; }
    else                 { G = g_BW11; base = ((size_t)cta * 8 + c) * 4096; }
    *reinterpret_cast<uint4*>(G + base + (size_t)nloc * 128 + ks)     = p0.v;
    *reinterpret_cast<uint4*>(G + base + (size_t)nloc * 128 + ks + 8) = p1.v;
}

// =====================================================================
// k_pre: HMMA input-gate precompute (proven R13, unchanged)
// =====================================================================
__global__ void __launch_bounds__(256) k_pre(const int* __restrict__ tokens) {
    extern __shared__ char sm[];
    const uint32_t smb = smem_u32(sm);
    const int tid = threadIdx.x, lane = tid & 31, warp = tid >> 5;
    const int t = blockIdx.x, n0 = blockIdx.y;
    const int M0 = (warp & 3) * 16, N0 = (warp >> 2) * 32;
    int* sTok = (int*)(sm + PC_TOK);

    if (tid < 64) sTok[tid] = tokens[tid * SS + t];
    __syncthreads();

    float acc[4][4];
#pragma unroll
    for (int i = 0; i < 4; i++)
#pragma unroll
        for (int j = 0; j < 4; j++) acc[i][j] = 0.0f;

    const __half* wb = g_Wx + (size_t)n0 * 64 * EE;

#pragma unroll 1
    for (int pre = 0; pre < 2; pre++) {
        const uint32_t sb = smb + pre * PC_STG;
        int kbase = pre * 128;
#pragma unroll
        for (int i = tid; i < 1024; i += 256) {
            int row = i >> 4, s = i & 15;
            uint32_t so = (uint32_t)row * 272 + (s << 4);
            cpa16(sb + so, (const char*)(g_emb16 + (size_t)sTok[row] * EE + kbase) + (s << 4));
            cpa16(sb + 17408 + so, (const char*)(wb + (size_t)row * EE + kbase) + (s << 4));
        }
        CP_COMMIT();
    }

#pragma unroll 1
    for (int c = 0; c < 4; c++) {
        if (c < 3) cp_wait<1>(); else cp_wait<0>();
        __syncthreads();
        const uint32_t sb = smb + (c & 1) * PC_STG;
        const uint32_t aoff = (uint32_t)(M0 + (lane & 15)) * 272 + ((lane >> 4) << 4);
        const uint32_t boff = (uint32_t)(N0 + (((lane >> 4) & 1) << 3) + (lane & 7)) * 272 +
                              (((lane >> 3) & 1) << 4);
#pragma unroll
        for (int ksi = 0; ksi < 8; ksi++) {
            const uint32_t kb = ksi << 5;
            uint32_t ah[4], bh[8];
            ldsm4(ah, sb + aoff + kb);
            ldsm4(bh, sb + 17408 + boff + kb);
            ldsm4(bh + 4, sb + 17408 + boff + 4352 + kb);
#pragma unroll
            for (int nt = 0; nt < 4; nt++)
                mma_f16(acc[nt], ah, bh[2 * nt], bh[2 * nt + 1]);
        }
        __syncthreads();
        if (c + 2 < 4) {
            const uint32_t sb2 = smb + ((c + 2) & 1) * PC_STG;
            int kbase = (c + 2) * 128;
#pragma unroll
            for (int i = tid; i < 1024; i += 256) {
                int row = i >> 4, s = i & 15;
                uint32_t so = (uint32_t)row * 272 + (s << 4);
                cpa16(sb2 + so, (const char*)(g_emb16 + (size_t)sTok[row] * EE + kbase) + (s << 4));
                cpa16(sb2 + 17408 + so, (const char*)(wb + (size_t)row * EE + kbase) + (s << 4));
            }
            CP_COMMIT();
        }
    }

    const int r0 = M0 + (lane >> 2);
#pragma unroll
    for (int nt = 0; nt < 4; nt++) {
        int col = n0 * 64 + N0 + nt * 8 + (lane & 3) * 2;
        size_t o0 = ((size_t)t * BB + r0) * GG + col;
        size_t o1 = ((size_t)t * BB + r0 + 8) * GG + col;
        const float* sp0 = g_sp + r0 * GG + col;
        const float* sp1 = g_sp + (r0 + 8) * GG + col;
        *reinterpret_cast<float2*>(g_P0 + o0) =
            make_float2(acc[nt][0] + sp0[0], acc[nt][1] + sp0[1]);
        *reinterpret_cast<float2*>(g_P0 + o1) =
            make_float2(acc[nt][2] + sp1[0], acc[nt][3] + sp1[1]);
    }
}

// =====================================================================
// k_steps building blocks
// =====================================================================
__device__ __forceinline__ void copy_A64(uint32_t sb, int ktid,
                                         const __half* gA, int kbase) {
#pragma unroll
    for (int i = ktid; i < 1024; i += 256) {
        int row = i >> 4, s = i & 15;
        uint32_t so = (uint32_t)row * 272 + (s << 4);
        cpa16(sb + so, (const char*)(gA + (size_t)row * HH + kbase) + (s << 4));
    }
}
__device__ __forceinline__ void copy_B64(uint32_t sb, int ktid, const __half* gB) {
#pragma unroll
    for (int i = ktid; i < 1024; i += 256) {
        int row = i >> 4, s = i & 15;
        uint32_t so = (uint32_t)row * 272 + (s << 4);
        cpa16(sb + 17408 + so, (const char*)gB + ((size_t)i << 4));
    }
}
__device__ __forceinline__ void copy_B32(uint32_t sb, int ktid, const __half* gB) {
#pragma unroll
    for (int i = ktid; i < 512; i += 256) {
        int row = i >> 4, s = i & 15;
        uint32_t so = (uint32_t)row * 272 + (s << 4);
        cpa16(sb + 17408 + so, (const char*)gB + ((size_t)i << 4));
    }
}

__device__ __forceinline__ void compute64(uint32_t sb, int lane, int M0, int N0,
                                          float acc[4][4]) {
    const uint32_t aoff = (uint32_t)(M0 + (lane & 15)) * 272 + ((lane >> 4) << 4);
    const uint32_t boff = (uint32_t)(N0 + (((lane >> 4) & 1) << 3) + (lane & 7)) * 272 +
                          (((lane >> 3) & 1) << 4);
#pragma unroll
    for (int ksi = 0; ksi < 8; ksi++) {
        const uint32_t kb = ksi << 5;
        uint32_t ah[4], bh[8];
        ldsm4(ah, sb + aoff + kb);
        ldsm4(bh, sb + 17408 + boff + kb);
        ldsm4(bh + 4, sb + 17408 + boff + 4352 + kb);
#pragma unroll
        for (int nt = 0; nt < 4; nt++)
            mma_f16(acc[nt], ah, bh[2 * nt], bh[2 * nt + 1]);
    }
}
__device__ __forceinline__ void compute32(uint32_t sb, int lane, int M0, int N0,
                                          float acc[2][4]) {
    const uint32_t aoff = (uint32_t)(M0 + (lane & 15)) * 272 + ((lane >> 4) << 4);
    const uint32_t boff = (uint32_t)(N0 + (((lane >> 4) & 1) << 3) + (lane & 7)) * 272 +
                          (((lane >> 3) & 1) << 4);
#pragma unroll
    for (int ksi = 0; ksi < 8; ksi++) {
        const uint32_t kb = ksi << 5;
        uint32_t ah[4], bh[4];
        ldsm4(ah, sb + aoff + kb);
        ldsm4(bh, sb + 17408 + boff + kb);
#pragma unroll
        for (int nt = 0; nt < 2; nt++)
            mma_f16(acc[nt], ah, bh[2 * nt], bh[2 * nt + 1]);
    }
}

// =====================================================================
// k_steps: persistent fused-phase kernel. grid 128, 512 threads.
// Phase p (p=-1..255): GEMM1 = H0[p] @ [W_hh0|W_ih1] (N=64),
//                      GEMM2 = H1[p-1] @ W_hh1      (N=32, p>=0),
// one split-K pipeline (2 kgroups x 3 stages), ONE grid barrier per phase.
// B tiles for next phase's chunks 0/1 are prefetched BEFORE the grid
// barrier (weights don't depend on h); A parts issued after.
// =====================================================================
__global__ void __launch_bounds__(512, 1) k_steps(
    const float* __restrict__ enc_c,
    const float* __restrict__ b_ih1, const float* __restrict__ b_hh1,
    float* __restrict__ out) {
    extern __shared__ char sm[];
    const uint32_t smb = smem_u32(sm);
    const int tid = threadIdx.x, lane = tid & 31, warp = tid >> 5;
    const int kg = warp >> 3, wl = warp & 7, ktid = tid & 255;
    const int cta = blockIdx.x, hu0 = cta * UPC;
    const int M0 = (wl & 3) * 16;
    const int N64 = (wl >> 2) * 32, N32 = (wl >> 2) * 16;

    float* sP  = (float*)(sm + SP_OFF);
    float* sc0 = (float*)(sm + SC0_OFF);
    float* sc1 = (float*)(sm + SC1_OFF);
    float* sB1 = (float*)(sm + SB1_OFF);

    {
        int m = tid >> 3, u = tid & 7;
        sc0[tid] = enc_c[m * HH + hu0 + u];
        sc1[tid] = enc_c[BB * HH + m * HH + hu0 + u];
    }
    if (tid < 32) {
        int col = (tid >> 3) * HH + hu0 + (tid & 7);
        sB1[tid] = b_ih1[col] + b_hh1[col];
    }
    __syncthreads();

    const __half* gBW01 = g_BW01 + (size_t)cta * 8 * 8192;
    const __half* gBW11 = g_BW11 + (size_t)cta * 8 * 4096;

    const int ep_m = tid >> 3, ep_u = tid & 7;
    const int pj = tid & 7, pq = pj >> 1, poff = (pj & 1) * 4;
    float* D1[2] = { (float*)sm, (float*)(sm + 3 * STG64) };
    float* D2[2] = { (float*)(sm + 16896), (float*)(sm + 3 * STG64 + 16896) };
    const uint32_t st0 = smb + (kg * 3) * STG64;
    const uint32_t st1 = smb + (kg * 3 + 1) * STG64;

    // prologue prefetch for phase -1 (full chunks 0/1 + P0[t=0])
    {
        copy_A64(st0, ktid, g_h0[1], kg * 128);
        copy_B64(st0, ktid, gBW01 + (size_t)kg * 8192);
        const float* src = g_P0 + (size_t)ep_m * GG + pq * HH + hu0 + poff;
        cpa16(smb + SP_OFF + (uint32_t)tid * 16, src);
        CP_COMMIT();
        copy_A64(st1, ktid, g_h0[1], (kg + 2) * 128);
        copy_B64(st1, ktid, gBW01 + (size_t)(kg + 2) * 8192);
        CP_COMMIT();
    }

#pragma unroll 1
    for (int p = -1; p < SS; p++) {
        const int nch = (p < 0) ? 4 : 8;
        const __half* A1 = g_h0[p & 1];
        const __half* A2 = g_h1[(p - 1) & 1];

        float acc1[4][4], acc2[2][4];
#pragma unroll
        for (int i = 0; i < 4; i++)
#pragma unroll
            for (int j = 0; j < 4; j++) acc1[i][j] = 0.0f;
#pragma unroll
        for (int i = 0; i < 2; i++)
#pragma unroll
            for (int j = 0; j < 4; j++) acc2[i][j] = 0.0f;

#pragma unroll 1
        for (int idx = 0; idx < nch; idx++) {
            if (idx < nch - 1) cp_wait<1>(); else cp_wait<0>();
            bar_kg(kg);
            uint32_t sb = smb + (kg * 3 + (idx % 3)) * STG64;
            if (idx < 4) compute64(sb, lane, M0, N64, acc1);
            else         compute32(sb, lane, M0, N32, acc2);
            if (idx + 2 < nch) {
                int nx = idx + 2;
                uint32_t sb2 = smb + (kg * 3 + (nx % 3)) * STG64;
                if (nx < 4) {
                    int c = 2 * nx + kg;
                    copy_A64(sb2, ktid, A1, c * 128);
                    copy_B64(sb2, ktid, gBW01 + (size_t)c * 8192);
                } else {
                    int c = 2 * (nx - 4) + kg;
                    copy_A64(sb2, ktid, A2, c * 128);
                    copy_B32(sb2, ktid, gBW11 + (size_t)c * 4096);
                }
                CP_COMMIT();
            }
        }
        __syncthreads();   // all stage reads done -> overlay D on stage mem

        {
            float* d1 = D1[kg];
            int r0 = M0 + (lane >> 2);
#pragma unroll
            for (int nt = 0; nt < 4; nt++) {
                int col = N64 + nt * 8 + (lane & 3) * 2;
                *reinterpret_cast<float2*>(&d1[r0 * 66 + col]) =
                    make_float2(acc1[nt][0], acc1[nt][1]);
                *reinterpret_cast<float2*>(&d1[(r0 + 8) * 66 + col]) =
                    make_float2(acc1[nt][2], acc1[nt][3]);
            }
            if (p >= 0) {
                float* d2 = D2[kg];
#pragma unroll
                for (int nt = 0; nt < 2; nt++) {
                    int col = N32 + nt * 8 + (lane & 3) * 2;
                    *reinterpret_cast<float2*>(&d2[r0 * 34 + col]) =
                        make_float2(acc2[nt][0], acc2[nt][1]);
                    *reinterpret_cast<float2*>(&d2[(r0 + 8) * 34 + col]) =
                        make_float2(acc2[nt][2], acc2[nt][3]);
                }
            }
        }
        __syncthreads();

        // ---- epilogue: layer0 (step p+1) ----
        {
            const float* a = D1[0] + ep_m * 66;
            const float* b = D1[1] + ep_m * 66;
            const float* sPm = sP + ep_m * 32;
            float gi = a[ep_u]      + b[ep_u]      + sPm[ep_u];
            float gf = a[8 + ep_u]  + b[8 + ep_u]  + sPm[8 + ep_u];
            float gg = a[16 + ep_u] + b[16 + ep_u] + sPm[16 + ep_u];
            float go = a[24 + ep_u] + b[24 + ep_u] + sPm[24 + ep_u];
            float cn = sigf(gf) * sc0[tid] + sigf(gi) * tanhf(gg);
            sc0[tid] = cn;
            g_h0[(p + 1) & 1][ep_m * HH + hu0 + ep_u] =
                __float2half(sigf(go) * tanhf(cn));
        }
        // ---- epilogue: layer1 (step p) ----
        if (p >= 0) {
            const float* a = D1[0] + ep_m * 66 + 32;
            const float* b = D1[1] + ep_m * 66 + 32;
            const float* c2a = D2[0] + ep_m * 34;
            const float* c2b = D2[1] + ep_m * 34;
            float gi = a[ep_u]      + b[ep_u]      + c2a[ep_u]      + c2b[ep_u]      + sB1[ep_u];
            float gf = a[8 + ep_u]  + b[8 + ep_u]  + c2a[8 + ep_u]  + c2b[8 + ep_u]  + sB1[8 + ep_u];
            float gg = a[16 + ep_u] + b[16 + ep_u] + c2a[16 + ep_u] + c2b[16 + ep_u] + sB1[16 + ep_u];
            float go = a[24 + ep_u] + b[24 + ep_u] + c2a[24 + ep_u] + c2b[24 + ep_u] + sB1[24 + ep_u];
            float cn = sigf(gf) * sc1[tid] + sigf(gi) * tanhf(gg);
            sc1[tid] = cn;
            float hv = sigf(go) * tanhf(cn);
            int hidx = ep_m * HH + hu0 + ep_u;
            g_h1[p & 1][hidx] = __float2half(hv);
            out[(size_t)p * BB * HH + hidx] = hv;
        }

        // ---- pre-barrier: prefetch next phase's B tiles (h-independent).
        // D overlays (incl. D2 overlapping stage B areas) are dead after the
        // epilogue; the __syncthreads protects the last readers.
        if (p + 1 < SS) {
            __syncthreads();
            copy_B64(st0, ktid, gBW01 + (size_t)kg * 8192);
            CP_COMMIT();
            copy_B64(st1, ktid, gBW01 + (size_t)(kg + 2) * 8192);
            CP_COMMIT();
        }
        grid_bar(tid, (unsigned)(p + 2));
        // ---- post-barrier: A parts for next phase's chunks 0/1 + P0 ----
        if (p + 1 < SS) {
            const __half* A1n = g_h0[(p + 1) & 1];
            copy_A64(st0, ktid, A1n, kg * 128);
            {
                int tP = (p + 2 < SS) ? p + 2 : SS - 1;
                const float* src = g_P0 + ((size_t)tP * BB + ep_m) * GG +
                                   pq * HH + hu0 + poff;
                cpa16(smb + SP_OFF + (uint32_t)tid * 16, src);
            }
            CP_COMMIT();
            copy_A64(st1, ktid, A1n, (kg + 2) * 128);
            CP_COMMIT();
        }
    }
}

// =====================================================================
extern "C" void kernel_launch(void* const* d_in, const int* in_sizes, int n_in,
                              void* d_out, int out_size) {
    const int*   tok      = (const int*)d_in[0];
    const int*   src      = (const int*)d_in[1];
    const float* enc_outs = (const float*)d_in[2];
    const float* enc_h    = (const float*)d_in[3];
    const float* enc_c    = (const float*)d_in[4];
    const float* embed    = (const float*)d_in[5];
    const float* W_ih0    = (const float*)d_in[6];
    const float* W_hh0    = (const float*)d_in[7];
    const float* b_ih0    = (const float*)d_in[8];
    const float* b_hh0    = (const float*)d_in[9];
    const float* W_ih1    = (const float*)d_in[10];
    const float* W_hh1    = (const float*)d_in[11];
    const float* b_ih1    = (const float*)d_in[12];
    const float* b_hh1    = (const float*)d_in[13];
    float* out = (float*)d_out;

    cudaFuncSetAttribute(k_steps, cudaFuncAttributeMaxDynamicSharedMemorySize, DYN_STEPS);
    cudaFuncSetAttribute(k_pre, cudaFuncAttributeMaxDynamicSharedMemorySize, DYN_PRE);

    k_emb16<<<32000 * EE / 2048, 256>>>(embed);
    k_static<<<dim3(GG / 256, BB / 8), 256>>>(enc_outs, src, embed, W_ih0, b_ih0, b_hh0);
    k_prep<<<dim3(8, NCTA, 4), 256>>>(W_hh0, W_ih1, W_hh1, W_ih0, enc_h);
    k_pre<<<dim3(SS, 64), 256, DYN_PRE>>>(tok);
    k_steps<<<NCTA, 512, DYN_STEPS>>>(enc_c, b_ih1, b_hh1, out);
}